// round 1
// baseline (speedup 1.0000x reference)
#include <cuda_runtime.h>
#include <cuda_bf16.h>
#include <cstdint>

// Problem constants (fixed shapes)
#define NN      50000
#define EE      800000
#define IN_C    64
#define EDGE_C  32
#define OUT_C   64
#define TILE_E  64          // edges per block-tile
#define N_TILES (EE / TILE_E)   // 12500 exactly

// Scratch (device globals; no runtime allocation allowed)
__device__ float g_A[NN * OUT_C];      // x @ W1[0:64]
__device__ float g_B[NN * OUT_C];      // x @ W1[64:128]
__device__ float g_cnt[NN];            // in-degree (float)

// ---------------------------------------------------------------------------
// vector reduction-add to global (sm_90+): 1 instruction per 4 floats
// ---------------------------------------------------------------------------
__device__ __forceinline__ void red_add_v4(float* p, float4 v) {
    asm volatile("red.global.add.v4.f32 [%0], {%1, %2, %3, %4};"
                 :: "l"(p), "f"(v.x), "f"(v.y), "f"(v.z), "f"(v.w)
                 : "memory");
}

// ---------------------------------------------------------------------------
// Kernel 0: zero out + count
// ---------------------------------------------------------------------------
__global__ void zero_kernel(float* __restrict__ out) {
    int id = blockIdx.x * blockDim.x + threadIdx.x;
    // out: NN*OUT_C = 3.2M floats = 800k float4
    if (id < (NN * OUT_C) / 4) {
        reinterpret_cast<float4*>(out)[id] = make_float4(0.f, 0.f, 0.f, 0.f);
    }
    if (id < NN) g_cnt[id] = 0.f;
}

// ---------------------------------------------------------------------------
// Kernel 1: per-node precompute  A = x @ W1a,  B = x @ W1b
// Block: 256 threads, tile = 64 nodes. Thread: 4 channels (tc) x 4 nodes (tn).
// smem: W1a (16KB) + W1b (16KB) + x tile (16KB) = 48KB static.
// ---------------------------------------------------------------------------
__global__ __launch_bounds__(256)
void pre_kernel(const float* __restrict__ x, const float* __restrict__ W1) {
    __shared__ float Wa_s[IN_C * OUT_C];
    __shared__ float Wb_s[IN_C * OUT_C];
    __shared__ float x_s[64 * IN_C];

    int t = threadIdx.x;
    for (int i = t; i < IN_C * OUT_C; i += 256) {
        Wa_s[i] = W1[i];                    // rows 0..63
        Wb_s[i] = W1[IN_C * OUT_C + i];     // rows 64..127
    }
    __syncthreads();

    const int tc = t & 15;     // channel group: channels 4*tc..4*tc+3
    const int tn = t >> 4;     // node group:    nodes    4*tn..4*tn+3

    int tile = blockIdx.x;     // grid sized to cover all tiles
    {
        int base = tile * 64;
        // stage 64 node rows of x (coalesced float4)
        const float4* x4 = reinterpret_cast<const float4*>(x);
        float4* xs4 = reinterpret_cast<float4*>(x_s);
        #pragma unroll
        for (int i = 0; i < 4; i++) {
            int id = t + 256 * i;            // 0..1023
            int n = id >> 4, q = id & 15;
            int gn = base + n;
            float4 v = make_float4(0.f, 0.f, 0.f, 0.f);
            if (gn < NN) v = x4[gn * 16 + q];
            xs4[n * 16 + q] = v;
        }
        __syncthreads();

        float4 aA[4], aB[4];
        #pragma unroll
        for (int n = 0; n < 4; n++) {
            aA[n] = make_float4(0.f, 0.f, 0.f, 0.f);
            aB[n] = make_float4(0.f, 0.f, 0.f, 0.f);
        }
        const float4* wa4 = reinterpret_cast<const float4*>(Wa_s);
        const float4* wb4 = reinterpret_cast<const float4*>(Wb_s);
        #pragma unroll 8
        for (int k = 0; k < IN_C; k++) {
            float4 wa = wa4[k * 16 + tc];
            float4 wb = wb4[k * 16 + tc];
            #pragma unroll
            for (int n = 0; n < 4; n++) {
                float v = x_s[(4 * tn + n) * IN_C + k];
                aA[n].x += v * wa.x; aA[n].y += v * wa.y;
                aA[n].z += v * wa.z; aA[n].w += v * wa.w;
                aB[n].x += v * wb.x; aB[n].y += v * wb.y;
                aB[n].z += v * wb.z; aB[n].w += v * wb.w;
            }
        }
        float4* A4 = reinterpret_cast<float4*>(g_A);
        float4* B4 = reinterpret_cast<float4*>(g_B);
        #pragma unroll
        for (int n = 0; n < 4; n++) {
            int gn = base + 4 * tn + n;
            if (gn < NN) {
                A4[gn * 16 + tc] = aA[n];
                B4[gn * 16 + tc] = aB[n];
            }
        }
    }
}

// ---------------------------------------------------------------------------
// Kernel 2: fused edge kernel.
// Per tile of 64 edges:
//   h  = relu(A[row] + B[col] + b1 + ea @ W1c)
//   m  = h @ W2 + b2
//   out[col] += m  (red.v4), cnt[col] += 1
// Thread mapping: tc = 4 channels, te = 4 edges -> 16 float accumulators.
// Dynamic smem: Wc(8K) + W2(16K) + ea(8K) + h(16K) + idx(0.5K) = 49664 B.
// ---------------------------------------------------------------------------
__global__ __launch_bounds__(256)
void edge_kernel(const int* __restrict__ row, const int* __restrict__ col,
                 const float* __restrict__ ea,
                 const float* __restrict__ W1, const float* __restrict__ b1,
                 const float* __restrict__ W2, const float* __restrict__ b2,
                 float* __restrict__ out) {
    extern __shared__ float sm[];
    float* Wc_s = sm;                 // [32][64]
    float* W2_s = sm + 2048;          // [64][64]
    float* ea_s = sm + 6144;          // [64 edges][32]
    float* h_s  = sm + 8192;          // [64 edges][64]
    int*   row_s = reinterpret_cast<int*>(sm + 12288);  // [64]
    int*   col_s = row_s + 64;                           // [64]

    const int t = threadIdx.x;
    // one-time weight staging
    for (int i = t; i < 32 * 64; i += 256) Wc_s[i] = W1[128 * 64 + i];
    for (int i = t; i < 64 * 64; i += 256) W2_s[i] = W2[i];
    __syncthreads();

    const int tc = t & 15;     // channels 4*tc..4*tc+3
    const int te = t >> 4;     // edges (within tile) 4*te..4*te+3

    const float4 b1v = *reinterpret_cast<const float4*>(b1 + 4 * tc);
    const float4 b2v = *reinterpret_cast<const float4*>(b2 + 4 * tc);

    const float4* Wc4 = reinterpret_cast<const float4*>(Wc_s);
    const float4* W24 = reinterpret_cast<const float4*>(W2_s);
    const float4* A4  = reinterpret_cast<const float4*>(g_A);
    const float4* B4  = reinterpret_cast<const float4*>(g_B);

    for (int tile = blockIdx.x; tile < N_TILES; tile += gridDim.x) {
        const int base = tile * TILE_E;

        // ---- stage indices + edge_attr tile ----
        if (t < 64) { row_s[t] = row[base + t]; col_s[t] = col[base + t]; }
        {
            const float4* eg4 = reinterpret_cast<const float4*>(ea) +
                                (size_t)base * (EDGE_C / 4);
            float4* es4 = reinterpret_cast<float4*>(ea_s);
            es4[t]       = eg4[t];
            es4[t + 256] = eg4[t + 256];
        }
        __syncthreads();

        // ---- layer 1: acc = A[row] + B[col] + b1 + ea @ W1c ----
        float4 acc[4];
        #pragma unroll
        for (int e = 0; e < 4; e++) {
            const int ed = 4 * te + e;
            const int r = row_s[ed], c = col_s[ed];
            float4 a = A4[r * 16 + tc];
            float4 b = B4[c * 16 + tc];
            acc[e] = make_float4(a.x + b.x + b1v.x, a.y + b.y + b1v.y,
                                 a.z + b.z + b1v.z, a.w + b.w + b1v.w);
        }
        #pragma unroll 8
        for (int k = 0; k < EDGE_C; k++) {
            float4 w = Wc4[k * 16 + tc];
            #pragma unroll
            for (int e = 0; e < 4; e++) {
                float v = ea_s[(4 * te + e) * EDGE_C + k];
                acc[e].x += v * w.x; acc[e].y += v * w.y;
                acc[e].z += v * w.z; acc[e].w += v * w.w;
            }
        }
        // relu, publish h (natural [edge][channel] layout: conflict-free STS.128)
        #pragma unroll
        for (int e = 0; e < 4; e++) {
            float4 h = make_float4(fmaxf(acc[e].x, 0.f), fmaxf(acc[e].y, 0.f),
                                   fmaxf(acc[e].z, 0.f), fmaxf(acc[e].w, 0.f));
            reinterpret_cast<float4*>(h_s)[(4 * te + e) * 16 + tc] = h;
        }
        __syncthreads();

        // ---- layer 2: m = h @ W2 ----
        float4 acc2[4];
        #pragma unroll
        for (int e = 0; e < 4; e++) acc2[e] = make_float4(0.f, 0.f, 0.f, 0.f);
        #pragma unroll 8
        for (int k = 0; k < OUT_C; k++) {
            float4 w = W24[k * 16 + tc];
            #pragma unroll
            for (int e = 0; e < 4; e++) {
                float v = h_s[(4 * te + e) * OUT_C + k];
                acc2[e].x += v * w.x; acc2[e].y += v * w.y;
                acc2[e].z += v * w.z; acc2[e].w += v * w.w;
            }
        }

        // ---- scatter: out[col] += m + b2 ; cnt[col] += 1 ----
        #pragma unroll
        for (int e = 0; e < 4; e++) {
            const int ed = 4 * te + e;
            const int c = col_s[ed];
            float4 m = make_float4(acc2[e].x + b2v.x, acc2[e].y + b2v.y,
                                   acc2[e].z + b2v.z, acc2[e].w + b2v.w);
            red_add_v4(out + (size_t)c * OUT_C + 4 * tc, m);
        }
        if (tc == 0) {
            #pragma unroll
            for (int e = 0; e < 4; e++) atomicAdd(&g_cnt[col_s[4 * te + e]], 1.0f);
        }
        __syncthreads();   // protect ea_s/h_s/idx before next tile's staging
    }
}

// ---------------------------------------------------------------------------
// Kernel 3: finalize — divide by clamped degree
// ---------------------------------------------------------------------------
__global__ void finalize_kernel(float* __restrict__ out) {
    int id = blockIdx.x * blockDim.x + threadIdx.x;   // over float4 elements
    if (id < (NN * OUT_C) / 4) {
        int n = id >> 4;
        float c = fmaxf(g_cnt[n], 1.0f);
        float4 v = reinterpret_cast<float4*>(out)[id];
        float inv = 1.0f / c;
        v.x *= inv; v.y *= inv; v.z *= inv; v.w *= inv;
        reinterpret_cast<float4*>(out)[id] = v;
    }
}

// ---------------------------------------------------------------------------
// Launch
// ---------------------------------------------------------------------------
extern "C" void kernel_launch(void* const* d_in, const int* in_sizes, int n_in,
                              void* d_out, int out_size) {
    const float* x    = (const float*)d_in[0];
    const int*   eidx = (const int*)d_in[1];     // [2][E]: row then col
    const float* ea   = (const float*)d_in[2];
    const float* W1   = (const float*)d_in[3];
    const float* b1   = (const float*)d_in[4];
    const float* W2   = (const float*)d_in[5];
    const float* b2   = (const float*)d_in[6];
    float* out = (float*)d_out;

    const int* row = eidx;
    const int* col = eidx + EE;

    // edge kernel needs 49664 B dynamic smem (> 48KB default)
    static_assert((12288 + 128) * 4 == 49664, "smem layout");
    cudaFuncSetAttribute(edge_kernel,
                         cudaFuncAttributeMaxDynamicSharedMemorySize, 49664);

    // 0) zero out + counts (out is poisoned by harness)
    {
        int total = (NN * OUT_C) / 4;           // 800k threads (also covers NN)
        zero_kernel<<<(total + 255) / 256, 256>>>(out);
    }
    // 1) per-node projections A, B
    {
        int tiles = (NN + 63) / 64;             // 782
        pre_kernel<<<tiles, 256>>>(x, W1);
    }
    // 2) fused edge MLP + scatter
    edge_kernel<<<592, 256, 49664>>>(row, col, ea, W1, b1, W2, b2, out);
    // 3) mean
    {
        int total = (NN * OUT_C) / 4;
        finalize_kernel<<<(total + 255) / 256, 256>>>(out);
    }
}

// round 2
// speedup vs baseline: 1.0188x; 1.0188x over previous
#include <cuda_runtime.h>
#include <cuda_bf16.h>
#include <cstdint>

// Problem constants (fixed shapes)
#define NN      50000
#define EE      800000
#define IN_C    64
#define EDGE_C  32
#define OUT_C   64
#define TILE_E  64
#define N_TILES (EE / TILE_E)   // 12500 exactly

// Scratch (device globals; no runtime allocation allowed)
__device__ float g_A[NN * OUT_C];      // x @ W1[0:64]
__device__ float g_B[NN * OUT_C];      // x @ W1[64:128]
__device__ float g_cnt[NN];            // in-degree (float)

typedef unsigned long long u64;

// ---------------------------------------------------------------------------
// packed fp32x2 helpers (Blackwell FFMA2 path)
// ---------------------------------------------------------------------------
__device__ __forceinline__ u64 pack2(float lo, float hi) {
    u64 r; asm("mov.b64 %0, {%1, %2};" : "=l"(r) : "f"(lo), "f"(hi)); return r;
}
__device__ __forceinline__ u64 dup2(float v) {
    u64 r; asm("mov.b64 %0, {%1, %1};" : "=l"(r) : "f"(v)); return r;
}
__device__ __forceinline__ void fma2(u64& d, u64 a, u64 b) {
    asm("fma.rn.f32x2 %0, %1, %2, %0;" : "+l"(d) : "l"(a), "l"(b));
}
__device__ __forceinline__ float2 unpack2(u64 v) {
    float2 f; asm("mov.b64 {%0, %1}, %2;" : "=f"(f.x), "=f"(f.y) : "l"(v)); return f;
}

// vector reduction-add to global: 1 instruction per 4 floats
__device__ __forceinline__ void red_add_v4(float* p, float4 v) {
    asm volatile("red.global.add.v4.f32 [%0], {%1, %2, %3, %4};"
                 :: "l"(p), "f"(v.x), "f"(v.y), "f"(v.z), "f"(v.w)
                 : "memory");
}

// ---------------------------------------------------------------------------
// Kernel 0: zero out + count
// ---------------------------------------------------------------------------
__global__ void zero_kernel(float* __restrict__ out) {
    int id = blockIdx.x * blockDim.x + threadIdx.x;
    if (id < (NN * OUT_C) / 4) {
        reinterpret_cast<float4*>(out)[id] = make_float4(0.f, 0.f, 0.f, 0.f);
    }
    if (id < NN) g_cnt[id] = 0.f;
}

// ---------------------------------------------------------------------------
// Kernel 1: per-node precompute  A = x @ W1a,  B = x @ W1b   (FFMA2 version)
// Block: 256 threads, tile = 64 nodes. Thread: 4 channels (tc) x 4 nodes (tn).
// ---------------------------------------------------------------------------
__global__ __launch_bounds__(256)
void pre_kernel(const float* __restrict__ x, const float* __restrict__ W1) {
    __shared__ float Wa_s[IN_C * OUT_C];
    __shared__ float Wb_s[IN_C * OUT_C];
    __shared__ float x_s[64 * IN_C];

    int t = threadIdx.x;
    for (int i = t; i < IN_C * OUT_C; i += 256) {
        Wa_s[i] = W1[i];                    // rows 0..63
        Wb_s[i] = W1[IN_C * OUT_C + i];     // rows 64..127
    }
    __syncthreads();

    const int tc = t & 15;     // channel group: channels 4*tc..4*tc+3
    const int tn = t >> 4;     // node group:    nodes    4*tn..4*tn+3

    const int base = blockIdx.x * 64;
    // stage 64 node rows of x (coalesced float4)
    {
        const float4* x4 = reinterpret_cast<const float4*>(x);
        float4* xs4 = reinterpret_cast<float4*>(x_s);
        #pragma unroll
        for (int i = 0; i < 4; i++) {
            int id = t + 256 * i;            // 0..1023
            int n = id >> 4, q = id & 15;
            int gn = base + n;
            float4 v = make_float4(0.f, 0.f, 0.f, 0.f);
            if (gn < NN) v = x4[gn * 16 + q];
            xs4[n * 16 + q] = v;
        }
    }
    __syncthreads();

    u64 aAL[4], aAH[4], aBL[4], aBH[4];
    #pragma unroll
    for (int n = 0; n < 4; n++) { aAL[n] = 0; aAH[n] = 0; aBL[n] = 0; aBH[n] = 0; }

    const ulonglong2* wa2 = reinterpret_cast<const ulonglong2*>(Wa_s);
    const ulonglong2* wb2 = reinterpret_cast<const ulonglong2*>(Wb_s);
    const float4* xs4 = reinterpret_cast<const float4*>(x_s);

    #pragma unroll
    for (int kb = 0; kb < IN_C / 4; kb++) {          // 16 blocks of 4 k
        ulonglong2 wa[4], wb[4];
        #pragma unroll
        for (int kk = 0; kk < 4; kk++) {
            wa[kk] = wa2[(4 * kb + kk) * 16 + tc];
            wb[kk] = wb2[(4 * kb + kk) * 16 + tc];
        }
        #pragma unroll
        for (int n = 0; n < 4; n++) {
            float4 v4 = xs4[(4 * tn + n) * 16 + kb];
            u64 d0 = dup2(v4.x), d1 = dup2(v4.y), d2 = dup2(v4.z), d3 = dup2(v4.w);
            fma2(aAL[n], d0, wa[0].x); fma2(aAH[n], d0, wa[0].y);
            fma2(aBL[n], d0, wb[0].x); fma2(aBH[n], d0, wb[0].y);
            fma2(aAL[n], d1, wa[1].x); fma2(aAH[n], d1, wa[1].y);
            fma2(aBL[n], d1, wb[1].x); fma2(aBH[n], d1, wb[1].y);
            fma2(aAL[n], d2, wa[2].x); fma2(aAH[n], d2, wa[2].y);
            fma2(aBL[n], d2, wb[2].x); fma2(aBH[n], d2, wb[2].y);
            fma2(aAL[n], d3, wa[3].x); fma2(aAH[n], d3, wa[3].y);
            fma2(aBL[n], d3, wb[3].x); fma2(aBH[n], d3, wb[3].y);
        }
    }

    float4* A4 = reinterpret_cast<float4*>(g_A);
    float4* B4 = reinterpret_cast<float4*>(g_B);
    #pragma unroll
    for (int n = 0; n < 4; n++) {
        int gn = base + 4 * tn + n;
        if (gn < NN) {
            float2 al = unpack2(aAL[n]), ah = unpack2(aAH[n]);
            float2 bl = unpack2(aBL[n]), bh = unpack2(aBH[n]);
            A4[gn * 16 + tc] = make_float4(al.x, al.y, ah.x, ah.y);
            B4[gn * 16 + tc] = make_float4(bl.x, bl.y, bh.x, bh.y);
        }
    }
}

// ---------------------------------------------------------------------------
// Kernel 2: fused edge kernel (FFMA2 version).
// Per tile of 64 edges:
//   h  = relu(A[row] + B[col] + b1 + ea @ W1c)
//   m  = h @ W2 + b2
//   out[col] += m  (red.v4), cnt[col] += 1
// Thread mapping: tc = 4 channels, te = 4 edges.
// Dynamic smem: Wc(8K) + W2(16K) + ea(8K) + h(16K) + idx(0.5K) = 49664 B.
// ---------------------------------------------------------------------------
__global__ __launch_bounds__(256)
void edge_kernel(const int* __restrict__ row, const int* __restrict__ col,
                 const float* __restrict__ ea,
                 const float* __restrict__ W1, const float* __restrict__ b1,
                 const float* __restrict__ W2, const float* __restrict__ b2,
                 float* __restrict__ out) {
    extern __shared__ float sm[];
    float* Wc_s = sm;                 // [32][64]
    float* W2_s = sm + 2048;          // [64][64]
    float* ea_s = sm + 6144;          // [64 edges][32]
    float* h_s  = sm + 8192;          // [64 edges][64]
    int*   row_s = reinterpret_cast<int*>(sm + 12288);  // [64]
    int*   col_s = row_s + 64;                           // [64]

    const int t = threadIdx.x;
    for (int i = t; i < 32 * 64; i += 256) Wc_s[i] = W1[128 * 64 + i];
    for (int i = t; i < 64 * 64; i += 256) W2_s[i] = W2[i];
    __syncthreads();

    const int tc = t & 15;     // channels 4*tc..4*tc+3
    const int te = t >> 4;     // edges (within tile) 4*te..4*te+3

    const float4 b1v = *reinterpret_cast<const float4*>(b1 + 4 * tc);
    const float4 b2v = *reinterpret_cast<const float4*>(b2 + 4 * tc);

    const ulonglong2* Wc2 = reinterpret_cast<const ulonglong2*>(Wc_s);
    const ulonglong2* W22 = reinterpret_cast<const ulonglong2*>(W2_s);
    const float4* A4  = reinterpret_cast<const float4*>(g_A);
    const float4* B4  = reinterpret_cast<const float4*>(g_B);
    const float4* ea4s = reinterpret_cast<const float4*>(ea_s);
    const float4* h4s  = reinterpret_cast<const float4*>(h_s);

    for (int tile = blockIdx.x; tile < N_TILES; tile += gridDim.x) {
        const int base = tile * TILE_E;

        // ---- stage indices + edge_attr tile ----
        if (t < 64) { row_s[t] = row[base + t]; col_s[t] = col[base + t]; }
        {
            const float4* eg4 = reinterpret_cast<const float4*>(ea) +
                                (size_t)base * (EDGE_C / 4);
            float4* es4 = reinterpret_cast<float4*>(ea_s);
            es4[t]       = eg4[t];
            es4[t + 256] = eg4[t + 256];
        }
        __syncthreads();

        // ---- layer 1: acc = A[row] + B[col] + b1 + ea @ W1c ----
        u64 accL[4], accH[4];
        #pragma unroll
        for (int e = 0; e < 4; e++) {
            const int ed = 4 * te + e;
            const int r = row_s[ed], c = col_s[ed];
            float4 a = A4[r * 16 + tc];
            float4 b = B4[c * 16 + tc];
            accL[e] = pack2(a.x + b.x + b1v.x, a.y + b.y + b1v.y);
            accH[e] = pack2(a.z + b.z + b1v.z, a.w + b.w + b1v.w);
        }
        #pragma unroll
        for (int kb = 0; kb < EDGE_C / 4; kb++) {     // 8 blocks of 4 k
            ulonglong2 w[4];
            #pragma unroll
            for (int kk = 0; kk < 4; kk++) w[kk] = Wc2[(4 * kb + kk) * 16 + tc];
            #pragma unroll
            for (int e = 0; e < 4; e++) {
                float4 v4 = ea4s[(4 * te + e) * 8 + kb];
                u64 d0 = dup2(v4.x), d1 = dup2(v4.y), d2 = dup2(v4.z), d3 = dup2(v4.w);
                fma2(accL[e], d0, w[0].x); fma2(accH[e], d0, w[0].y);
                fma2(accL[e], d1, w[1].x); fma2(accH[e], d1, w[1].y);
                fma2(accL[e], d2, w[2].x); fma2(accH[e], d2, w[2].y);
                fma2(accL[e], d3, w[3].x); fma2(accH[e], d3, w[3].y);
            }
        }
        // relu, publish h ([edge][channel] layout: conflict-free STS.128)
        #pragma unroll
        for (int e = 0; e < 4; e++) {
            float2 lo = unpack2(accL[e]), hi = unpack2(accH[e]);
            float4 h = make_float4(fmaxf(lo.x, 0.f), fmaxf(lo.y, 0.f),
                                   fmaxf(hi.x, 0.f), fmaxf(hi.y, 0.f));
            reinterpret_cast<float4*>(h_s)[(4 * te + e) * 16 + tc] = h;
        }
        __syncthreads();

        // ---- layer 2: m = h @ W2 ----
        u64 acc2L[4], acc2H[4];
        #pragma unroll
        for (int e = 0; e < 4; e++) { acc2L[e] = 0; acc2H[e] = 0; }
        #pragma unroll
        for (int kb = 0; kb < OUT_C / 4; kb++) {      // 16 blocks of 4 k
            ulonglong2 w[4];
            #pragma unroll
            for (int kk = 0; kk < 4; kk++) w[kk] = W22[(4 * kb + kk) * 16 + tc];
            #pragma unroll
            for (int e = 0; e < 4; e++) {
                float4 v4 = h4s[(4 * te + e) * 16 + kb];
                u64 d0 = dup2(v4.x), d1 = dup2(v4.y), d2 = dup2(v4.z), d3 = dup2(v4.w);
                fma2(acc2L[e], d0, w[0].x); fma2(acc2H[e], d0, w[0].y);
                fma2(acc2L[e], d1, w[1].x); fma2(acc2H[e], d1, w[1].y);
                fma2(acc2L[e], d2, w[2].x); fma2(acc2H[e], d2, w[2].y);
                fma2(acc2L[e], d3, w[3].x); fma2(acc2H[e], d3, w[3].y);
            }
        }

        // ---- scatter: out[col] += m + b2 ; cnt[col] += 1 ----
        #pragma unroll
        for (int e = 0; e < 4; e++) {
            const int ed = 4 * te + e;
            const int c = col_s[ed];
            float2 lo = unpack2(acc2L[e]), hi = unpack2(acc2H[e]);
            float4 m = make_float4(lo.x + b2v.x, lo.y + b2v.y,
                                   hi.x + b2v.z, hi.y + b2v.w);
            red_add_v4(out + (size_t)c * OUT_C + 4 * tc, m);
        }
        if (tc == 0) {
            #pragma unroll
            for (int e = 0; e < 4; e++) atomicAdd(&g_cnt[col_s[4 * te + e]], 1.0f);
        }
        __syncthreads();   // protect ea_s/h_s/idx before next tile's staging
    }
}

// ---------------------------------------------------------------------------
// Kernel 3: finalize — divide by clamped degree
// ---------------------------------------------------------------------------
__global__ void finalize_kernel(float* __restrict__ out) {
    int id = blockIdx.x * blockDim.x + threadIdx.x;   // over float4 elements
    if (id < (NN * OUT_C) / 4) {
        int n = id >> 4;
        float c = fmaxf(g_cnt[n], 1.0f);
        float4 v = reinterpret_cast<float4*>(out)[id];
        float inv = 1.0f / c;
        v.x *= inv; v.y *= inv; v.z *= inv; v.w *= inv;
        reinterpret_cast<float4*>(out)[id] = v;
    }
}

// ---------------------------------------------------------------------------
// Launch
// ---------------------------------------------------------------------------
extern "C" void kernel_launch(void* const* d_in, const int* in_sizes, int n_in,
                              void* d_out, int out_size) {
    const float* x    = (const float*)d_in[0];
    const int*   eidx = (const int*)d_in[1];     // [2][E]: row then col
    const float* ea   = (const float*)d_in[2];
    const float* W1   = (const float*)d_in[3];
    const float* b1   = (const float*)d_in[4];
    const float* W2   = (const float*)d_in[5];
    const float* b2   = (const float*)d_in[6];
    float* out = (float*)d_out;

    const int* row = eidx;
    const int* col = eidx + EE;

    static_assert((12288 + 128) * 4 == 49664, "smem layout");
    cudaFuncSetAttribute(edge_kernel,
                         cudaFuncAttributeMaxDynamicSharedMemorySize, 49664);

    // 0) zero out + counts (out is poisoned by harness)
    {
        int total = (NN * OUT_C) / 4;
        zero_kernel<<<(total + 255) / 256, 256>>>(out);
    }
    // 1) per-node projections A, B
    {
        int tiles = (NN + 63) / 64;             // 782
        pre_kernel<<<tiles, 256>>>(x, W1);
    }
    // 2) fused edge MLP + scatter
    edge_kernel<<<592, 256, 49664>>>(row, col, ea, W1, b1, W2, b2, out);
    // 3) mean
    {
        int total = (NN * OUT_C) / 4;
        finalize_kernel<<<(total + 255) / 256, 256>>>(out);
    }
}

// round 3
// speedup vs baseline: 1.8047x; 1.7713x over previous
#include <cuda_runtime.h>
#include <cuda_bf16.h>
#include <cstdint>

// Problem constants (fixed shapes)
#define NN      50000
#define EE      800000
#define IN_C    64
#define EDGE_C  32
#define OUT_C   64
#define TILE_E  64
#define N_TILES (EE / TILE_E)   // 12500 exactly

// Scratch (device globals; 16B-aligned for v4 access)
__device__ __align__(16) float g_A[NN * OUT_C];   // x @ W1[0:64]
__device__ __align__(16) float g_B[NN * OUT_C];   // x @ W1[64:128]
__device__ __align__(16) float g_H[NN * OUT_C];   // scatter-sum of relu(h)
__device__ float g_cnt[NN];                        // in-degree (float)

typedef unsigned long long u64;

// ---------------------------------------------------------------------------
// packed fp32x2 helpers
// ---------------------------------------------------------------------------
__device__ __forceinline__ u64 pack2(float lo, float hi) {
    u64 r; asm("mov.b64 %0, {%1, %2};" : "=l"(r) : "f"(lo), "f"(hi)); return r;
}
__device__ __forceinline__ u64 dup2(float v) {
    u64 r; asm("mov.b64 %0, {%1, %1};" : "=l"(r) : "f"(v)); return r;
}
__device__ __forceinline__ void fma2(u64& d, u64 a, u64 b) {
    asm("fma.rn.f32x2 %0, %1, %2, %0;" : "+l"(d) : "l"(a), "l"(b));
}
__device__ __forceinline__ float2 unpack2(u64 v) {
    float2 f; asm("mov.b64 {%0, %1}, %2;" : "=f"(f.x), "=f"(f.y) : "l"(v)); return f;
}

// vector reduction-add to global: 1 instruction per 4 floats
__device__ __forceinline__ void red_add_v4(float* p, float4 v) {
    asm volatile("red.global.add.v4.f32 [%0], {%1, %2, %3, %4};"
                 :: "l"(p), "f"(v.x), "f"(v.y), "f"(v.z), "f"(v.w)
                 : "memory");
}

// ---------------------------------------------------------------------------
// Kernel 0: zero H accumulator + counts
// ---------------------------------------------------------------------------
__global__ void zero_kernel() {
    int id = blockIdx.x * blockDim.x + threadIdx.x;
    if (id < (NN * OUT_C) / 4) {
        reinterpret_cast<float4*>(g_H)[id] = make_float4(0.f, 0.f, 0.f, 0.f);
    }
    if (id < NN) g_cnt[id] = 0.f;
}

// ---------------------------------------------------------------------------
// Kernel 1: per-node precompute  A = x @ W1a,  B = x @ W1b
// Block: 256 threads, tile = 64 nodes. Thread: 4 channels (tc) x 4 nodes (tn).
// ---------------------------------------------------------------------------
__global__ __launch_bounds__(256)
void pre_kernel(const float* __restrict__ x, const float* __restrict__ W1) {
    __shared__ float Wa_s[IN_C * OUT_C];
    __shared__ float Wb_s[IN_C * OUT_C];
    __shared__ float x_s[64 * IN_C];

    int t = threadIdx.x;
    for (int i = t; i < IN_C * OUT_C; i += 256) {
        Wa_s[i] = W1[i];                    // rows 0..63
        Wb_s[i] = W1[IN_C * OUT_C + i];     // rows 64..127
    }

    const int tc = t & 15;
    const int tn = t >> 4;
    const int base = blockIdx.x * 64;
    {
        const float4* x4 = reinterpret_cast<const float4*>(x);
        float4* xs4 = reinterpret_cast<float4*>(x_s);
        #pragma unroll
        for (int i = 0; i < 4; i++) {
            int id = t + 256 * i;
            int n = id >> 4, q = id & 15;
            int gn = base + n;
            float4 v = make_float4(0.f, 0.f, 0.f, 0.f);
            if (gn < NN) v = x4[gn * 16 + q];
            xs4[n * 16 + q] = v;
        }
    }
    __syncthreads();

    u64 aAL[4], aAH[4], aBL[4], aBH[4];
    #pragma unroll
    for (int n = 0; n < 4; n++) { aAL[n] = 0; aAH[n] = 0; aBL[n] = 0; aBH[n] = 0; }

    const ulonglong2* wa2 = reinterpret_cast<const ulonglong2*>(Wa_s);
    const ulonglong2* wb2 = reinterpret_cast<const ulonglong2*>(Wb_s);
    const float4* xs4 = reinterpret_cast<const float4*>(x_s);

    #pragma unroll
    for (int kb = 0; kb < IN_C / 4; kb++) {
        ulonglong2 wa[4], wb[4];
        #pragma unroll
        for (int kk = 0; kk < 4; kk++) {
            wa[kk] = wa2[(4 * kb + kk) * 16 + tc];
            wb[kk] = wb2[(4 * kb + kk) * 16 + tc];
        }
        #pragma unroll
        for (int n = 0; n < 4; n++) {
            float4 v4 = xs4[(4 * tn + n) * 16 + kb];
            u64 d0 = dup2(v4.x), d1 = dup2(v4.y), d2 = dup2(v4.z), d3 = dup2(v4.w);
            fma2(aAL[n], d0, wa[0].x); fma2(aAH[n], d0, wa[0].y);
            fma2(aBL[n], d0, wb[0].x); fma2(aBH[n], d0, wb[0].y);
            fma2(aAL[n], d1, wa[1].x); fma2(aAH[n], d1, wa[1].y);
            fma2(aBL[n], d1, wb[1].x); fma2(aBH[n], d1, wb[1].y);
            fma2(aAL[n], d2, wa[2].x); fma2(aAH[n], d2, wa[2].y);
            fma2(aBL[n], d2, wb[2].x); fma2(aBH[n], d2, wb[2].y);
            fma2(aAL[n], d3, wa[3].x); fma2(aAH[n], d3, wa[3].y);
            fma2(aBL[n], d3, wb[3].x); fma2(aBH[n], d3, wb[3].y);
        }
    }

    float4* A4 = reinterpret_cast<float4*>(g_A);
    float4* B4 = reinterpret_cast<float4*>(g_B);
    #pragma unroll
    for (int n = 0; n < 4; n++) {
        int gn = base + 4 * tn + n;
        if (gn < NN) {
            float2 al = unpack2(aAL[n]), ah = unpack2(aAH[n]);
            float2 bl = unpack2(aBL[n]), bh = unpack2(aBH[n]);
            A4[gn * 16 + tc] = make_float4(al.x, al.y, ah.x, ah.y);
            B4[gn * 16 + tc] = make_float4(bl.x, bl.y, bh.x, bh.y);
        }
    }
}

// ---------------------------------------------------------------------------
// Kernel 2: edge kernel (layer 1 only).
// Per tile of 64 edges:
//   h  = relu(A[row] + B[col] + b1 + ea @ W1c)
//   g_H[col] += h  (red.v4), cnt[col] += 1
// Static smem: Wc(8K) + ea(8K) + idx(0.5K).
// ---------------------------------------------------------------------------
__global__ __launch_bounds__(256)
void edge_kernel(const int* __restrict__ row, const int* __restrict__ col,
                 const float* __restrict__ ea,
                 const float* __restrict__ W1, const float* __restrict__ b1) {
    __shared__ float Wc_s[EDGE_C * OUT_C];
    __shared__ float ea_s[TILE_E * EDGE_C];
    __shared__ int row_s[TILE_E];
    __shared__ int col_s[TILE_E];

    const int t = threadIdx.x;
    for (int i = t; i < EDGE_C * OUT_C; i += 256) Wc_s[i] = W1[128 * 64 + i];

    const int tc = t & 15;     // channels 4*tc..4*tc+3
    const int te = t >> 4;     // edges (within tile) 4*te..4*te+3

    const float4 b1v = *reinterpret_cast<const float4*>(b1 + 4 * tc);

    const ulonglong2* Wc2 = reinterpret_cast<const ulonglong2*>(Wc_s);
    const float4* A4  = reinterpret_cast<const float4*>(g_A);
    const float4* B4  = reinterpret_cast<const float4*>(g_B);
    const float4* ea4s = reinterpret_cast<const float4*>(ea_s);

    for (int tile = blockIdx.x; tile < N_TILES; tile += gridDim.x) {
        const int base = tile * TILE_E;

        __syncthreads();   // protect ea_s / idx from previous iteration readers
        if (t < 64) { row_s[t] = row[base + t]; col_s[t] = col[base + t]; }
        {
            const float4* eg4 = reinterpret_cast<const float4*>(ea) +
                                (size_t)base * (EDGE_C / 4);
            float4* es4 = reinterpret_cast<float4*>(ea_s);
            es4[t]       = eg4[t];
            es4[t + 256] = eg4[t + 256];
        }
        __syncthreads();

        // acc = A[row] + B[col] + b1 + ea @ W1c
        u64 accL[4], accH[4];
        int cdst[4];
        #pragma unroll
        for (int e = 0; e < 4; e++) {
            const int ed = 4 * te + e;
            const int r = row_s[ed], c = col_s[ed];
            cdst[e] = c;
            float4 a = A4[r * 16 + tc];
            float4 b = B4[c * 16 + tc];
            accL[e] = pack2(a.x + b.x + b1v.x, a.y + b.y + b1v.y);
            accH[e] = pack2(a.z + b.z + b1v.z, a.w + b.w + b1v.w);
        }
        #pragma unroll
        for (int kb = 0; kb < EDGE_C / 4; kb++) {
            ulonglong2 w[4];
            #pragma unroll
            for (int kk = 0; kk < 4; kk++) w[kk] = Wc2[(4 * kb + kk) * 16 + tc];
            #pragma unroll
            for (int e = 0; e < 4; e++) {
                float4 v4 = ea4s[(4 * te + e) * 8 + kb];
                u64 d0 = dup2(v4.x), d1 = dup2(v4.y), d2 = dup2(v4.z), d3 = dup2(v4.w);
                fma2(accL[e], d0, w[0].x); fma2(accH[e], d0, w[0].y);
                fma2(accL[e], d1, w[1].x); fma2(accH[e], d1, w[1].y);
                fma2(accL[e], d2, w[2].x); fma2(accH[e], d2, w[2].y);
                fma2(accL[e], d3, w[3].x); fma2(accH[e], d3, w[3].y);
            }
        }

        // relu + scatter h into g_H[col]
        #pragma unroll
        for (int e = 0; e < 4; e++) {
            float2 lo = unpack2(accL[e]), hi = unpack2(accH[e]);
            float4 h = make_float4(fmaxf(lo.x, 0.f), fmaxf(lo.y, 0.f),
                                   fmaxf(hi.x, 0.f), fmaxf(hi.y, 0.f));
            red_add_v4(g_H + (size_t)cdst[e] * OUT_C + 4 * tc, h);
        }
        if (tc == 0) {
            #pragma unroll
            for (int e = 0; e < 4; e++) atomicAdd(&g_cnt[cdst[e]], 1.0f);
        }
    }
}

// ---------------------------------------------------------------------------
// Kernel 3: node GEMM + mean + bias:  out = (H @ W2) / max(cnt,1) + b2
//           (zero-degree nodes output exactly 0, matching reference)
// Block: 256 threads, tile = 64 nodes.
// ---------------------------------------------------------------------------
__global__ __launch_bounds__(256)
void out_kernel(const float* __restrict__ W2, const float* __restrict__ b2,
                float* __restrict__ out) {
    __shared__ float W2_s[OUT_C * OUT_C];
    __shared__ float h_s[64 * OUT_C];

    const int t = threadIdx.x;
    for (int i = t; i < OUT_C * OUT_C; i += 256) W2_s[i] = W2[i];

    const int tc = t & 15;
    const int tn = t >> 4;
    const int base = blockIdx.x * 64;
    {
        const float4* H4 = reinterpret_cast<const float4*>(g_H);
        float4* hs4 = reinterpret_cast<float4*>(h_s);
        #pragma unroll
        for (int i = 0; i < 4; i++) {
            int id = t + 256 * i;
            int n = id >> 4, q = id & 15;
            int gn = base + n;
            float4 v = make_float4(0.f, 0.f, 0.f, 0.f);
            if (gn < NN) v = H4[gn * 16 + q];
            hs4[n * 16 + q] = v;
        }
    }
    __syncthreads();

    u64 aL[4], aH[4];
    #pragma unroll
    for (int n = 0; n < 4; n++) { aL[n] = 0; aH[n] = 0; }

    const ulonglong2* w2 = reinterpret_cast<const ulonglong2*>(W2_s);
    const float4* hs4 = reinterpret_cast<const float4*>(h_s);

    #pragma unroll
    for (int kb = 0; kb < OUT_C / 4; kb++) {
        ulonglong2 w[4];
        #pragma unroll
        for (int kk = 0; kk < 4; kk++) w[kk] = w2[(4 * kb + kk) * 16 + tc];
        #pragma unroll
        for (int n = 0; n < 4; n++) {
            float4 v4 = hs4[(4 * tn + n) * 16 + kb];
            u64 d0 = dup2(v4.x), d1 = dup2(v4.y), d2 = dup2(v4.z), d3 = dup2(v4.w);
            fma2(aL[n], d0, w[0].x); fma2(aH[n], d0, w[0].y);
            fma2(aL[n], d1, w[1].x); fma2(aH[n], d1, w[1].y);
            fma2(aL[n], d2, w[2].x); fma2(aH[n], d2, w[2].y);
            fma2(aL[n], d3, w[3].x); fma2(aH[n], d3, w[3].y);
        }
    }

    const float4 b2v = *reinterpret_cast<const float4*>(b2 + 4 * tc);
    float4* out4 = reinterpret_cast<float4*>(out);
    #pragma unroll
    for (int n = 0; n < 4; n++) {
        int gn = base + 4 * tn + n;
        if (gn < NN) {
            float c = g_cnt[gn];
            float2 lo = unpack2(aL[n]), hi = unpack2(aH[n]);
            float4 o;
            if (c < 0.5f) {
                o = make_float4(0.f, 0.f, 0.f, 0.f);   // zero-degree: reference gives 0
            } else {
                float inv = 1.0f / c;
                o = make_float4(lo.x * inv + b2v.x, lo.y * inv + b2v.y,
                                hi.x * inv + b2v.z, hi.y * inv + b2v.w);
            }
            out4[gn * 16 + tc] = o;
        }
    }
}

// ---------------------------------------------------------------------------
// Launch
// ---------------------------------------------------------------------------
extern "C" void kernel_launch(void* const* d_in, const int* in_sizes, int n_in,
                              void* d_out, int out_size) {
    const float* x    = (const float*)d_in[0];
    const int*   eidx = (const int*)d_in[1];     // [2][E]: row then col
    const float* ea   = (const float*)d_in[2];
    const float* W1   = (const float*)d_in[3];
    const float* b1   = (const float*)d_in[4];
    const float* W2   = (const float*)d_in[5];
    const float* b2   = (const float*)d_in[6];
    float* out = (float*)d_out;

    const int* row = eidx;
    const int* col = eidx + EE;

    // 0) zero H accumulator + counts
    {
        int total = (NN * OUT_C) / 4;           // covers NN too
        zero_kernel<<<(total + 255) / 256, 256>>>();
    }
    // 1) per-node projections A, B
    pre_kernel<<<(NN + 63) / 64, 256>>>(x, W1);
    // 2) edge layer-1 + scatter h
    edge_kernel<<<1184, 256>>>(row, col, ea, W1, b1);
    // 3) node GEMM + mean + bias
    out_kernel<<<(NN + 63) / 64, 256>>>(W2, b2, out);
}